// round 5
// baseline (speedup 1.0000x reference)
#include <cuda_runtime.h>

// out(n,h,w) = K * sum_{r,c} k[r][c] * inp(n, h+r, w+c)
// inp: (64, 512, 512, 1) f32, k: (3,3,1,1) f32, out: (64, 510, 510, 1) f32
// K = closed-form collapse of the 1000-step LIF recurrence (linear: I<9<14).
//
// R5: R3 scalar-FFMA structure (FFMA2 reverted — alu-pipe pack cost ate the
// gain) + streaming stores (__stcs: keep input L2-resident, evict-first for
// the write stream) + occupancy bump via __launch_bounds__(128, 12).

#define IN_H  512
#define IN_W  512
#define OUT_H 510
#define OUT_W 510
#define TILE_ROWS 4
#define TILES_Y   128            // 510/4 rounded up
#define N_IMG     64
#define TOTAL_TILES (N_IMG * TILES_Y)

__global__ void __launch_bounds__(128, 12) snn_conv_scale_kernel(
    const float* __restrict__ inp,
    const float* __restrict__ kw,
    float* __restrict__ out,
    float K)
{
    // weights premultiplied by K (uniform loads, hoisted out of tile loop)
    const float4 kA = *(const float4*)(kw);
    const float4 kB = *(const float4*)(kw + 4);
    const float  k8 = kw[8];
    const float wgt[3][3] = {
        { K*kA.x, K*kA.y, K*kA.z },
        { K*kA.w, K*kB.x, K*kB.y },
        { K*kB.z, K*kB.w, K*k8   }
    };

    const int w0 = threadIdx.x * 4;            // 0..508
    const bool has_b     = (w0 <= IN_W - 8);   // second float4 in-row
    const bool full128   = (w0 <= 504);        // full 4-wide stores valid
    const bool is_edge_r = (w0 == 508);        // even-row partial pair
    const bool is_edge_l = (w0 == 0);          // odd-row cols {0,1}

    for (int tile = blockIdx.x; tile < TOTAL_TILES; tile += gridDim.x) {
        const int n  = tile >> 7;              // tile / 128
        const int ty = tile & 127;
        const int h0 = ty * TILE_ROWS;         // 0,4,...,508

        const float* base = inp + ((size_t)n * IN_H + h0) * IN_W + w0;

        float acc[TILE_ROWS][4];
        #pragma unroll
        for (int oh = 0; oh < TILE_ROWS; ++oh)
            #pragma unroll
            for (int c = 0; c < 4; ++c) acc[oh][c] = 0.0f;
        float e1[2] = {0.f, 0.f}, e3[2] = {0.f, 0.f};   // odd-row cols {0,1}

        #pragma unroll
        for (int r = 0; r < TILE_ROWS + 2; ++r) {
            const int hin = h0 + r;
            float4 a = make_float4(0.f,0.f,0.f,0.f);
            float4 b = make_float4(0.f,0.f,0.f,0.f);
            if (hin < IN_H) {
                a = *(const float4*)(base + (size_t)r * IN_W);
                if (has_b) b = *(const float4*)(base + (size_t)r * IN_W + 4);
            }
            const float x[8] = { a.x, a.y, a.z, a.w, b.x, b.y, b.z, b.w };

            #pragma unroll
            for (int oh = 0; oh < TILE_ROWS; ++oh) {
                if (oh <= r && r <= oh + 2) {
                    const int kr = r - oh;                 // compile-time
                    const float wr0 = wgt[kr][0], wr1 = wgt[kr][1], wr2 = wgt[kr][2];
                    const int s = (oh & 1) ? 2 : 0;        // odd rows shifted +2
                    #pragma unroll
                    for (int c = 0; c < 4; ++c)
                        acc[oh][c] += wr0*x[s+c] + wr1*x[s+c+1] + wr2*x[s+c+2];
                    if ((oh & 1) && is_edge_l) {           // odd-row cols 0,1
                        float* e = (oh == 1) ? e1 : e3;
                        #pragma unroll
                        for (int c = 0; c < 2; ++c)
                            e[c] += wr0*x[c] + wr1*x[c+1] + wr2*x[c+2];
                    }
                }
            }
        }

        float* onb = out + (size_t)n * OUT_H * OUT_W;
        #pragma unroll
        for (int oh = 0; oh < TILE_ROWS; ++oh) {
            const int h = h0 + oh;
            if (h < OUT_H) {
                float* orow = onb + (size_t)h * OUT_W;
                if ((oh & 1) == 0) {
                    if (full128) {
                        __stcs((float4*)(orow + w0),
                               make_float4(acc[oh][0], acc[oh][1], acc[oh][2], acc[oh][3]));
                    } else if (is_edge_r) {                // cols 508,509
                        __stcs((float2*)(orow + 508), make_float2(acc[oh][0], acc[oh][1]));
                    }
                } else {
                    if (full128) {                         // cols w0+2..w0+5
                        __stcs((float4*)(orow + w0 + 2),
                               make_float4(acc[oh][0], acc[oh][1], acc[oh][2], acc[oh][3]));
                    }
                    if (is_edge_l) {                       // cols 0,1
                        const float* e = (oh == 1) ? e1 : e3;
                        __stcs((float2*)(orow), make_float2(e[0], e[1]));
                    }
                }
            }
        }
    }
}

// Closed-form LIF collapse: vt(I) = K * I. Deterministic, recomputed per call.
static double compute_K()
{
    const double DT = 0.01, R = 3000.0, C = 10.0;
    const double I = 1.0;
    double v = 0.0;
    v = v + (-v + R * I) / (R * C) * DT;   // v0; thresholds never fire
    double vt = v;
    for (int i = 0; i < 999; i++) {
        v = v + (-v + R * I) / (R * C) * DT;
        vt = (v + vt) / 1000.0;
    }
    return vt;
}

extern "C" void kernel_launch(void* const* d_in, const int* in_sizes, int n_in,
                              void* d_out, int out_size)
{
    const float* inp = (const float*)d_in[0];   // (64,512,512,1)
    const float* kw  = (const float*)d_in[1];   // (3,3,1,1)
    float* out = (float*)d_out;                 // (64,510,510,1)

    const float K = (float)compute_K();

    const int nblocks = 148 * 16;               // grid-stride persistent
    snn_conv_scale_kernel<<<nblocks, 128>>>(inp, kw, out, K);
}

// round 7
// speedup vs baseline: 1.2653x; 1.2653x over previous
#include <cuda_runtime.h>

// out(n,h,w) = K * sum_{r,c} k[r][c] * inp(n, h+r, w+c)
// inp: (64, 512, 512, 1) f32, k: (3,3,1,1) f32, out: (64, 510, 510, 1) f32
// K = closed-form collapse of the 1000-step LIF recurrence (linear: I<9<14).
//
// R6: exactly R3 (best known: parity-shifted STG.128 windows, grid-stride
// persistent) + ONE lever: occupancy. __launch_bounds__(128,12) caps regs at
// 42 (12 blocks/SM = 75% occ) and grid = 148*12 makes every block resident
// for the whole kernel (no launch tail). __stcs from R5 reverted (regressed).

#define IN_H  512
#define IN_W  512
#define OUT_H 510
#define OUT_W 510
#define TILE_ROWS 4
#define TILES_Y   128            // 510/4 rounded up
#define N_IMG     64
#define TOTAL_TILES (N_IMG * TILES_Y)

__global__ void __launch_bounds__(128, 12) snn_conv_scale_kernel(
    const float* __restrict__ inp,
    const float* __restrict__ kw,
    float* __restrict__ out,
    float K)
{
    // weights premultiplied by K (uniform loads, hoisted out of tile loop)
    const float4 kA = *(const float4*)(kw);
    const float4 kB = *(const float4*)(kw + 4);
    const float  k8 = kw[8];
    const float wgt[3][3] = {
        { K*kA.x, K*kA.y, K*kA.z },
        { K*kA.w, K*kB.x, K*kB.y },
        { K*kB.z, K*kB.w, K*k8   }
    };

    const int w0 = threadIdx.x * 4;            // 0..508
    const bool has_b     = (w0 <= IN_W - 8);   // second float4 in-row
    const bool full128   = (w0 <= 504);        // full 4-wide stores valid
    const bool is_edge_r = (w0 == 508);        // even-row partial pair
    const bool is_edge_l = (w0 == 0);          // odd-row cols {0,1}

    for (int tile = blockIdx.x; tile < TOTAL_TILES; tile += gridDim.x) {
        const int n  = tile >> 7;              // tile / 128
        const int ty = tile & 127;
        const int h0 = ty * TILE_ROWS;         // 0,4,...,508

        const float* base = inp + ((size_t)n * IN_H + h0) * IN_W + w0;

        float acc[TILE_ROWS][4];
        #pragma unroll
        for (int oh = 0; oh < TILE_ROWS; ++oh)
            #pragma unroll
            for (int c = 0; c < 4; ++c) acc[oh][c] = 0.0f;
        float e1[2] = {0.f, 0.f}, e3[2] = {0.f, 0.f};   // odd-row cols {0,1}

        #pragma unroll
        for (int r = 0; r < TILE_ROWS + 2; ++r) {
            const int hin = h0 + r;
            float4 a = make_float4(0.f,0.f,0.f,0.f);
            float4 b = make_float4(0.f,0.f,0.f,0.f);
            if (hin < IN_H) {
                a = *(const float4*)(base + (size_t)r * IN_W);
                if (has_b) b = *(const float4*)(base + (size_t)r * IN_W + 4);
            }
            const float x[8] = { a.x, a.y, a.z, a.w, b.x, b.y, b.z, b.w };

            #pragma unroll
            for (int oh = 0; oh < TILE_ROWS; ++oh) {
                if (oh <= r && r <= oh + 2) {
                    const int kr = r - oh;                 // compile-time
                    const float wr0 = wgt[kr][0], wr1 = wgt[kr][1], wr2 = wgt[kr][2];
                    const int s = (oh & 1) ? 2 : 0;        // odd rows shifted +2
                    #pragma unroll
                    for (int c = 0; c < 4; ++c)
                        acc[oh][c] += wr0*x[s+c] + wr1*x[s+c+1] + wr2*x[s+c+2];
                    if ((oh & 1) && is_edge_l) {           // odd-row cols 0,1
                        float* e = (oh == 1) ? e1 : e3;
                        #pragma unroll
                        for (int c = 0; c < 2; ++c)
                            e[c] += wr0*x[c] + wr1*x[c+1] + wr2*x[c+2];
                    }
                }
            }
        }

        float* onb = out + (size_t)n * OUT_H * OUT_W;
        #pragma unroll
        for (int oh = 0; oh < TILE_ROWS; ++oh) {
            const int h = h0 + oh;
            if (h < OUT_H) {
                float* orow = onb + (size_t)h * OUT_W;
                if ((oh & 1) == 0) {
                    if (full128) {
                        *(float4*)(orow + w0) =
                            make_float4(acc[oh][0], acc[oh][1], acc[oh][2], acc[oh][3]);
                    } else if (is_edge_r) {                // cols 508,509
                        *(float2*)(orow + 508) = make_float2(acc[oh][0], acc[oh][1]);
                    }
                } else {
                    if (full128) {                         // cols w0+2..w0+5
                        *(float4*)(orow + w0 + 2) =
                            make_float4(acc[oh][0], acc[oh][1], acc[oh][2], acc[oh][3]);
                    }
                    if (is_edge_l) {                       // cols 0,1
                        const float* e = (oh == 1) ? e1 : e3;
                        *(float2*)(orow) = make_float2(e[0], e[1]);
                    }
                }
            }
        }
    }
}

// Closed-form LIF collapse: vt(I) = K * I. Deterministic, recomputed per call.
static double compute_K()
{
    const double DT = 0.01, R = 3000.0, C = 10.0;
    const double I = 1.0;
    double v = 0.0;
    v = v + (-v + R * I) / (R * C) * DT;   // v0; thresholds never fire
    double vt = v;
    for (int i = 0; i < 999; i++) {
        v = v + (-v + R * I) / (R * C) * DT;
        vt = (v + vt) / 1000.0;
    }
    return vt;
}

extern "C" void kernel_launch(void* const* d_in, const int* in_sizes, int n_in,
                              void* d_out, int out_size)
{
    const float* inp = (const float*)d_in[0];   // (64,512,512,1)
    const float* kw  = (const float*)d_in[1];   // (3,3,1,1)
    float* out = (float*)d_out;                 // (64,510,510,1)

    const float K = (float)compute_K();

    const int nblocks = 148 * 12;               // exact residency: 12 blocks/SM
    snn_conv_scale_kernel<<<nblocks, 128>>>(inp, kw, out, K);
}